// round 17
// baseline (speedup 1.0000x reference)
#include <cuda_runtime.h>
#include <cuda_bf16.h>
#include <cstdint>

// Problem constants
#define BATCH   16
#define CDIM    64
#define HW      4096
#define KTOT    1024
#define NTOT    (BATCH*HW)
#define TM      128         // positions per block (M)
#define TN      128         // codes per chunk (N)
#define NCHUNK  (KTOT/TN)   // 8
#define NBLOCKS (NTOT/TM)   // 512
#define ELEMS   ((size_t)BATCH*CDIM*HW)   // 4194304

// Output layout: [loss(1)][quantized NCHW(4194304)][indices(65536)]
#define OUT_Q    1
#define OUT_IDX  (1 + (size_t)ELEMS)

// SMEM layout (bytes): A h/m/l [128j][64c] bf16; B h/m/l [128n][64c] bf16
#define A_TILE   16384
#define B_TILE   16384
#define OFF_A    0
#define OFF_B    (3*A_TILE)             // 49152
#define OFF_EN   (OFF_B + 3*B_TILE)     // 98304
#define OFF_XN   (OFF_EN + KTOT*4)      // 102400
#define OFF_IDXS (OFF_XN + TM*4)        // 102912
#define SMEM_TOTAL (OFF_IDXS + TM*4)    // 103424

#define SWZ(o) ((o) ^ (((o) >> 3) & 0x70))

// Device globals
__device__ __align__(16) __nv_bfloat16 g_eh[KTOT*CDIM];
__device__ __align__(16) __nv_bfloat16 g_em[KTOT*CDIM];
__device__ __align__(16) __nv_bfloat16 g_el[KTOT*CDIM];
__device__ __align__(16) float g_enorm[KTOT];
__device__ float g_scratch[NBLOCKS];
__device__ int   g_count = 0;

// ---------------- helpers ----------------
__device__ __forceinline__ uint32_t smem_u32(const void* p) {
    uint32_t a;
    asm("{ .reg .u64 t; cvta.to.shared.u64 t, %1; cvt.u32.u64 %0, t; }"
        : "=r"(a) : "l"(p));
    return a;
}
__device__ __forceinline__ void ldsm4(uint32_t* r, uint32_t addr) {
    asm volatile("ldmatrix.sync.aligned.m8n8.x4.shared.b16 {%0,%1,%2,%3}, [%4];"
                 : "=r"(r[0]), "=r"(r[1]), "=r"(r[2]), "=r"(r[3]) : "r"(addr));
}
__device__ __forceinline__ void mma_bf16(float* c, const uint32_t* a,
                                         uint32_t b0, uint32_t b1) {
    asm volatile(
        "mma.sync.aligned.m16n8k16.row.col.f32.bf16.bf16.f32 "
        "{%0,%1,%2,%3}, {%4,%5,%6,%7}, {%8,%9}, {%0,%1,%2,%3};"
        : "+f"(c[0]), "+f"(c[1]), "+f"(c[2]), "+f"(c[3])
        : "r"(a[0]), "r"(a[1]), "r"(a[2]), "r"(a[3]), "r"(b0), "r"(b1));
}
__device__ __forceinline__ void cp16(uint32_t dst, const void* src) {
    asm volatile("cp.async.cg.shared.global [%0], [%1], 16;"
                 :: "r"(dst), "l"(src) : "memory");
}
__device__ __forceinline__ void cp_wait_all() {
    asm volatile("cp.async.commit_group;\n\tcp.async.wait_group 0;" ::: "memory");
}

// ---------------- prep: bf16 3-split of embedding + norms ----------------
__global__ void vq_prep(const float* __restrict__ emb) {
    int t = threadIdx.x;
    int k = blockIdx.x * 16 + (t >> 4);
    int c = (t & 15) * 4;
    float4 v = *(const float4*)(emb + (size_t)k * CDIM + c);
    float vv[4] = {v.x, v.y, v.z, v.w};
    #pragma unroll
    for (int i = 0; i < 4; i++) {
        float x = vv[i];
        __nv_bfloat16 h = __float2bfloat16(x);
        float r = x - __bfloat162float(h);
        __nv_bfloat16 m = __float2bfloat16(r);
        float r2 = r - __bfloat162float(m);
        __nv_bfloat16 l = __float2bfloat16(r2);
        g_eh[(size_t)k * CDIM + c + i] = h;
        g_em[(size_t)k * CDIM + c + i] = m;
        g_el[(size_t)k * CDIM + c + i] = l;
    }
    float p = v.x * v.x + v.y * v.y + v.z * v.z + v.w * v.w;
    p += __shfl_xor_sync(0xffffffffu, p, 1);
    p += __shfl_xor_sync(0xffffffffu, p, 2);
    p += __shfl_xor_sync(0xffffffffu, p, 4);
    p += __shfl_xor_sync(0xffffffffu, p, 8);
    if ((t & 15) == 0) g_enorm[k] = p;
}

// ---------------- main: HMMA bf16 3-split GEMM + argmin ----------------
// aH/aM hoisted (32 regs); aL fragment reloaded per ks (4 regs).
// B fragments software-pipelined: bf[2][12] double register buffer.
__global__ __launch_bounds__(256, 2)
void vq_main(const float* __restrict__ xin_all, const float* __restrict__ emb,
             float* __restrict__ out) {
    extern __shared__ char smem[];
    const uint32_t sb = smem_u32(smem);
    float* xs    = (float*)(smem + OFF_B);     // fp32 staging in B region
    float* en_s  = (float*)(smem + OFF_EN);
    float* xn_s  = (float*)(smem + OFF_XN);
    int*   idx_s = (int*)(smem + OFF_IDXS);
    float* qs    = (float*)(smem + OFF_B);     // quantized staging (post-loop)

    const int tid = threadIdx.x;
    const int wid = tid >> 5;
    const int lid = tid & 31;
    const int b   = blockIdx.x >> 5;
    const int hw0 = (blockIdx.x & 31) * TM;
    const float* xin = xin_all + (size_t)b * CDIM * HW + hw0;

    // Load X tile fp32 [c][j] (coalesced) + enorm (full 1024)
    #pragma unroll
    for (int p = 0; p < 8; p++) {
        int c = (tid >> 5) + p * 8;
        int j = (tid & 31) * 4;
        *(float4*)(xs + c * TM + j) = *(const float4*)(xin + (size_t)c * HW + j);
    }
    *((float4*)en_s + tid) = *((const float4*)g_enorm + tid);
    __syncthreads();

    // Convert X -> 3 bf16 A tiles (swizzled) + fused ||x||^2
    {
        const int j  = tid >> 1;
        const int ch = (tid & 1) * 32;
        float nacc = 0.f;
        #pragma unroll
        for (int cc = 0; cc < 32; cc += 2) {
            int c = ch + cc;
            float v0 = xs[c * TM + j];
            float v1 = xs[(c + 1) * TM + j];
            nacc += v0 * v0 + v1 * v1;
            __nv_bfloat16 h0 = __float2bfloat16(v0);
            float r0 = v0 - __bfloat162float(h0);
            __nv_bfloat16 m0 = __float2bfloat16(r0);
            __nv_bfloat16 l0 = __float2bfloat16(r0 - __bfloat162float(m0));
            __nv_bfloat16 h1 = __float2bfloat16(v1);
            float r1 = v1 - __bfloat162float(h1);
            __nv_bfloat16 m1 = __float2bfloat16(r1);
            __nv_bfloat16 l1 = __float2bfloat16(r1 - __bfloat162float(m1));
            uint32_t off = SWZ((uint32_t)(j * 128 + c * 2));
            uint32_t ph = ((uint32_t)__bfloat16_as_ushort(h1) << 16) | __bfloat16_as_ushort(h0);
            uint32_t pm = ((uint32_t)__bfloat16_as_ushort(m1) << 16) | __bfloat16_as_ushort(m0);
            uint32_t pl = ((uint32_t)__bfloat16_as_ushort(l1) << 16) | __bfloat16_as_ushort(l0);
            *(uint32_t*)(smem + OFF_A + off)              = ph;
            *(uint32_t*)(smem + OFF_A + A_TILE + off)     = pm;
            *(uint32_t*)(smem + OFF_A + 2 * A_TILE + off) = pl;
        }
        nacc += __shfl_xor_sync(0xffffffffu, nacc, 1);
        if ((tid & 1) == 0) xn_s[j] = nacc;
    }
    __syncthreads();   // A tiles ready; xs (B region) free

    // ldmatrix lane address components
    const int wbase = wid * 16;
    const int lt = lid >> 3, lr = lid & 7;
    const int rowA  = wbase + lr + 8 * (lt & 1);
    const int colA8 = (lt >> 1) * 8;
    const int rowB  = lr + 8 * (lt >> 1);
    const int colB8 = (lt & 1) * 8;

    // Hoist aH, aM fragments (2 splits x 4 k-steps = 32 regs); aL per-ks.
    uint32_t aH[4][4], aM[4][4];
    uint32_t aoff[4];
    #pragma unroll
    for (int ks = 0; ks < 4; ks++) {
        aoff[ks] = SWZ((uint32_t)(rowA * 128 + ks * 32 + colA8 * 2));
        ldsm4(aH[ks], sb + OFF_A + aoff[ks]);
        ldsm4(aM[ks], sb + OFF_A + A_TILE + aoff[ks]);
    }

    float best0 = 3.4e38f, best1 = 3.4e38f;
    int   bidx0 = 0x7fffffff, bidx1 = 0x7fffffff;

    for (int chunk = 0; chunk < NCHUNK; chunk++) {
        const int kbase = chunk * TN;

        __syncthreads();   // all warps done reading previous B
        {
            const char* s0 = (const char*)(g_eh + (size_t)kbase * CDIM);
            const char* s1 = (const char*)(g_em + (size_t)kbase * CDIM);
            const char* s2 = (const char*)(g_el + (size_t)kbase * CDIM);
            #pragma unroll
            for (int i = 0; i < 4; i++) {
                uint32_t u = (uint32_t)(tid + 256 * i) * 16;
                uint32_t d = SWZ(u);
                cp16(sb + OFF_B + d,              s0 + u);
                cp16(sb + OFF_B + B_TILE + d,     s1 + u);
                cp16(sb + OFF_B + 2 * B_TILE + d, s2 + u);
            }
            cp_wait_all();
        }
        __syncthreads();

        #pragma unroll
        for (int half = 0; half < 2; half++) {
            float acc[32];
            #pragma unroll
            for (int i = 0; i < 32; i++) acc[i] = 0.f;

            uint32_t bf[2][12];
            uint32_t alK[4];
            // prologue: load B frags for it=0 (ks=0,ntp=0)
            {
                uint32_t bo = SWZ((uint32_t)((half * 64 + rowB) * 128 + colB8 * 2));
                ldsm4(&bf[0][0], sb + OFF_B + bo);
                ldsm4(&bf[0][4], sb + OFF_B + B_TILE + bo);
                ldsm4(&bf[0][8], sb + OFF_B + 2 * B_TILE + bo);
            }
            #pragma unroll
            for (int it = 0; it < 16; it++) {
                const int ks = it >> 2, ntp = it & 3;
                if (ntp == 0) ldsm4(alK, sb + OFF_A + 2 * A_TILE + aoff[ks]);
                if (it < 15) {
                    const int nit = it + 1;
                    const int nks = nit >> 2, nntp = nit & 3;
                    uint32_t bo = SWZ((uint32_t)((half * 64 + nntp * 16 + rowB) * 128
                                                 + nks * 32 + colB8 * 2));
                    uint32_t* nb = bf[nit & 1];
                    ldsm4(&nb[0], sb + OFF_B + bo);
                    ldsm4(&nb[4], sb + OFF_B + B_TILE + bo);
                    ldsm4(&nb[8], sb + OFF_B + 2 * B_TILE + bo);
                }
                const uint32_t* bb = bf[it & 1];
                float* a0 = &acc[ntp * 8];
                float* a1 = &acc[ntp * 8 + 4];
                mma_bf16(a0, aH[ks], bb[0], bb[1]);   // hh
                mma_bf16(a1, aH[ks], bb[2], bb[3]);
                mma_bf16(a0, aH[ks], bb[4], bb[5]);   // hm
                mma_bf16(a1, aH[ks], bb[6], bb[7]);
                mma_bf16(a0, aM[ks], bb[0], bb[1]);   // mh
                mma_bf16(a1, aM[ks], bb[2], bb[3]);
                mma_bf16(a0, aM[ks], bb[4], bb[5]);   // mm
                mma_bf16(a1, aM[ks], bb[6], bb[7]);
                mma_bf16(a0, aH[ks], bb[8], bb[9]);   // hl
                mma_bf16(a1, aH[ks], bb[10], bb[11]);
                mma_bf16(a0, alK,    bb[0], bb[1]);   // lh
                mma_bf16(a1, alK,    bb[2], bb[3]);
            }

            // scores: ||e||^2 - 2 dot ; nt ascending => k ascending (first-idx ties)
            #pragma unroll
            for (int nt = 0; nt < 8; nt++) {
                const int k = kbase + half * 64 + nt * 8 + 2 * (lid & 3);
                const float* ac = &acc[nt * 4];
                float e0 = en_s[k], e1 = en_s[k + 1];
                float s0 = e0 - (ac[0] + ac[0]);
                float s1 = e1 - (ac[1] + ac[1]);
                float s2 = e0 - (ac[2] + ac[2]);
                float s3 = e1 - (ac[3] + ac[3]);
                if (s0 < best0) { best0 = s0; bidx0 = k; }
                if (s1 < best0) { best0 = s1; bidx0 = k + 1; }
                if (s2 < best1) { best1 = s2; bidx1 = k; }
                if (s3 < best1) { best1 = s3; bidx1 = k + 1; }
            }
        }
    }

    // quad reduction (lanes sharing lid>>2 hold the same j rows)
    #pragma unroll
    for (int d = 1; d <= 2; d <<= 1) {
        float os = __shfl_xor_sync(0xffffffffu, best0, d);
        int   ok = __shfl_xor_sync(0xffffffffu, bidx0, d);
        if (os < best0 || (os == best0 && ok < bidx0)) { best0 = os; bidx0 = ok; }
        os = __shfl_xor_sync(0xffffffffu, best1, d);
        ok = __shfl_xor_sync(0xffffffffu, bidx1, d);
        if (os < best1 || (os == best1 && ok < bidx1)) { best1 = os; bidx1 = ok; }
    }
    if ((lid & 3) == 0) {
        int j0 = wbase + (lid >> 2);
        int j1 = j0 + 8;
        idx_s[j0] = bidx0;
        idx_s[j1] = bidx1;
        out[OUT_IDX + (size_t)b * HW + hw0 + j0] = (float)bidx0;
        out[OUT_IDX + (size_t)b * HW + hw0 + j1] = (float)bidx1;
        xn_s[j0] = best0 + xn_s[j0];   // dist = score + ||x||^2
        xn_s[j1] = best1 + xn_s[j1];
    }
    __syncthreads();

    // Gather emb rows (contiguous 256B) into qs [c][j]
    {
        const int jq = tid >> 1;
        const int c0 = (tid & 1) * 32;
        const int kq = idx_s[jq];
        const float4* erow = (const float4*)(emb + (size_t)kq * CDIM + c0);
        #pragma unroll
        for (int q = 0; q < 8; q++) {
            float4 v = erow[q];
            int c = c0 + q * 4;
            qs[(c + 0) * TM + jq] = v.x;
            qs[(c + 1) * TM + jq] = v.y;
            qs[(c + 2) * TM + jq] = v.z;
            qs[(c + 3) * TM + jq] = v.w;
        }
    }
    if (tid < 64) xn_s[tid] += xn_s[tid + 64];
    __syncthreads();

    if (tid < 32) {
        float v = xn_s[tid] + xn_s[tid + 32];
        v += __shfl_xor_sync(0xffffffffu, v, 16);
        v += __shfl_xor_sync(0xffffffffu, v, 8);
        v += __shfl_xor_sync(0xffffffffu, v, 4);
        v += __shfl_xor_sync(0xffffffffu, v, 2);
        v += __shfl_xor_sync(0xffffffffu, v, 1);
        if (tid == 0) g_scratch[blockIdx.x] = v;
    }

    // Quantized write — SCALAR stores (out+1 breaks 16B alignment)
    {
        float* qbase = out + OUT_Q + (size_t)b * CDIM * HW + hw0;
        const int lane = tid & 31;
        #pragma unroll
        for (int p = 0; p < 8; p++) {
            int c = (tid >> 5) + p * 8;
            #pragma unroll
            for (int q = 0; q < 4; q++) {
                int j = lane + q * 32;
                qbase[(size_t)c * HW + j] = qs[c * TM + j];
            }
        }
    }

    // ---- fused final loss ----
    __shared__ int s_last;
    __threadfence();
    if (tid == 0) {
        int old = atomicAdd(&g_count, 1);
        s_last = (old == NBLOCKS - 1) ? 1 : 0;
    }
    __syncthreads();
    if (s_last) {
        float v = g_scratch[tid] + g_scratch[tid + 256];
        v += __shfl_xor_sync(0xffffffffu, v, 16);
        v += __shfl_xor_sync(0xffffffffu, v, 8);
        v += __shfl_xor_sync(0xffffffffu, v, 4);
        v += __shfl_xor_sync(0xffffffffu, v, 2);
        v += __shfl_xor_sync(0xffffffffu, v, 1);
        if ((tid & 31) == 0) xn_s[tid >> 5] = v;
        __syncthreads();
        if (tid == 0) {
            float s = 0.f;
            #pragma unroll
            for (int w = 0; w < 8; w++) s += xn_s[w];
            out[0] = 0.25f * s / (float)ELEMS;
            g_count = 0;
        }
    }
}

extern "C" void kernel_launch(void* const* d_in, const int* in_sizes, int n_in,
                              void* d_out, int out_size) {
    const float* x   = (const float*)d_in[0];   // [16,64,64,64] NCHW
    const float* emb = (const float*)d_in[1];   // [1024,64]
    float* out = (float*)d_out;

    cudaFuncSetAttribute(vq_main, cudaFuncAttributeMaxDynamicSharedMemorySize,
                         SMEM_TOTAL);
    vq_prep<<<KTOT / 16, 256>>>(emb);
    vq_main<<<NBLOCKS, 256, SMEM_TOTAL>>>(x, emb, out);
}